// round 15
// baseline (speedup 1.0000x reference)
#include <cuda_runtime.h>
#include <cuda_bf16.h>
#include <cstddef>
#include <cstdint>

#define Bsz  32
#define Tt   1024
#define Ii   1024
#define Hh   256
#define NOUT 512   // 2*H
#define Mrows (Bsz * Tt)        // 32768
#define NKT0 16                 // 1024/64 k-tiles (layer0)
#define NKT1 8                  // 512/64 k-tiles (layer1)
#define TILEB 16384             // bytes per 128x64 bf16 tile
#define STAGEB 65536            // 4 tiles (Ahi,Alo,Whi,Wlo)
#define GEMM_SMEM (2 * STAGEB + 1024)

typedef unsigned long long ull;

// ---------------------------------------------------------------------------
// Device scratch (allocation-free rule: __device__ globals)
// ---------------------------------------------------------------------------
__device__ float g_xp[(size_t)Mrows * NOUT];                 // projections
__device__ __align__(256) __nv_bfloat16 g_Ahi[(size_t)Mrows * Ii];
__device__ __align__(256) __nv_bfloat16 g_Alo[(size_t)Mrows * Ii];
__device__ __align__(256) __nv_bfloat16 g_H1hi[(size_t)Mrows * NOUT];
__device__ __align__(256) __nv_bfloat16 g_H1lo[(size_t)Mrows * NOUT];
__device__ __align__(256) __nv_bfloat16 g_W0hi[NOUT * Ii];
__device__ __align__(256) __nv_bfloat16 g_W0lo[NOUT * Ii];
__device__ __align__(256) __nv_bfloat16 g_W1hi[NOUT * NOUT];
__device__ __align__(256) __nv_bfloat16 g_W1lo[NOUT * NOUT];

// ---------------------------------------------------------------------------
// Helpers
// ---------------------------------------------------------------------------
__device__ __forceinline__ uint32_t swz(uint32_t x) { return x ^ ((x >> 3) & 0x70); }

__device__ __forceinline__ void ffma2(ull& acc, ull a, ull b) {
    asm("fma.rn.f32x2 %0, %1, %2, %0;" : "+l"(acc) : "l"(a), "l"(b));
}
__device__ __forceinline__ float2 up2(ull v) {
    float2 r;
    asm("mov.b64 {%0, %1}, %2;" : "=f"(r.x), "=f"(r.y) : "l"(v));
    return r;
}
__device__ __forceinline__ float tanh_acc(float z) {
    float az = fabsf(z);
    float e  = exp2f(az * 2.885390081777927f);
    float r  = 1.0f - __fdividef(2.0f, e + 1.0f);
    return copysignf(r, z);
}
__device__ __forceinline__ uint32_t smem_u32(const void* p) {
    uint32_t a;
    asm("{ .reg .u64 t; cvta.to.shared.u64 t, %1; cvt.u32.u64 %0, t; }"
        : "=r"(a) : "l"(p));
    return a;
}

// generic tensor-core path (compute_80+ PTX, compiles at compute_103)
__device__ __forceinline__ void ldsm4(uint32_t* r, uint32_t addr) {
    asm volatile("ldmatrix.sync.aligned.m8n8.x4.shared.b16 {%0,%1,%2,%3}, [%4];"
                 : "=r"(r[0]), "=r"(r[1]), "=r"(r[2]), "=r"(r[3]) : "r"(addr));
}
__device__ __forceinline__ void mma_bf16(float* c, const uint32_t* a,
                                         uint32_t b0, uint32_t b1) {
    asm volatile(
        "mma.sync.aligned.m16n8k16.row.col.f32.bf16.bf16.f32 "
        "{%0,%1,%2,%3}, {%4,%5,%6,%7}, {%8,%9}, {%0,%1,%2,%3};"
        : "+f"(c[0]), "+f"(c[1]), "+f"(c[2]), "+f"(c[3])
        : "r"(a[0]), "r"(a[1]), "r"(a[2]), "r"(a[3]), "r"(b0), "r"(b1));
}
__device__ __forceinline__ void cp16(uint32_t sdst, const void* gsrc) {
    asm volatile("cp.async.cg.shared.global [%0], [%1], 16;"
                 :: "r"(sdst), "l"(gsrc) : "memory");
}
#define CP_COMMIT() asm volatile("cp.async.commit_group;" ::: "memory")
#define CP_WAIT(n)  asm volatile("cp.async.wait_group %0;" :: "n"(n) : "memory")

// ---------------------------------------------------------------------------
// fp32 -> (hi, lo) bf16 split, written into SW128-swizzled 128x64 tiles.
// ---------------------------------------------------------------------------
__global__ __launch_bounds__(256) void conv_bf16(
    const float* __restrict__ src,
    __nv_bfloat16* __restrict__ dhi,
    __nv_bfloat16* __restrict__ dlo,
    int K, int mode, int total)
{
    int idx = blockIdx.x * 256 + threadIdx.x;
    if (idx >= total) return;
    const int gpr = K >> 3;
    const int m = idx / gpr;
    const int k = (idx - m * gpr) << 3;

    const float* s = (mode == 0)
        ? src + (((size_t)(m & 31) * Tt + (m >> 5)) * K + k)
        : src + ((size_t)m * K + k);
    float4 v0 = *(const float4*)s;
    float4 v1 = *(const float4*)(s + 4);
    float f[8] = {v0.x, v0.y, v0.z, v0.w, v1.x, v1.y, v1.z, v1.w};

    uint32_t hw[4], lw[4];
    #pragma unroll
    for (int i = 0; i < 4; i++) {
        __nv_bfloat16 ha = __float2bfloat16_rn(f[2 * i]);
        __nv_bfloat16 hb = __float2bfloat16_rn(f[2 * i + 1]);
        __nv_bfloat16 la = __float2bfloat16_rn(f[2 * i]     - __bfloat162float(ha));
        __nv_bfloat16 lb = __float2bfloat16_rn(f[2 * i + 1] - __bfloat162float(hb));
        hw[i] = (uint32_t)__bfloat16_as_ushort(ha) | ((uint32_t)__bfloat16_as_ushort(hb) << 16);
        lw[i] = (uint32_t)__bfloat16_as_ushort(la) | ((uint32_t)__bfloat16_as_ushort(lb) << 16);
    }

    const int mt = m >> 7, r = m & 127, kt = k >> 6, c = k & 63;
    size_t off = ((size_t)(mt * (K >> 6) + kt)) * TILEB + swz((uint32_t)(r * 128 + c * 2));
    *(uint4*)((char*)dhi + off) = make_uint4(hw[0], hw[1], hw[2], hw[3]);
    *(uint4*)((char*)dlo + off) = make_uint4(lw[0], lw[1], lw[2], lw[3]);
}

// ---------------------------------------------------------------------------
// bf16x3 tensor-core GEMM (mma.sync): g_xp = A.W^T + b1 + b2   (unchanged)
// ---------------------------------------------------------------------------
__device__ __forceinline__ void stage_cp(
    uint32_t sdst, const char* pAh, const char* pAl,
    const char* pWh, const char* pWl, int tid)
{
    #pragma unroll
    for (int i = 0; i < 4; i++) {
        const int off = tid * 16 + i * 4096;
        cp16(sdst + off,         pAh + off);
        cp16(sdst + 16384 + off, pAl + off);
        cp16(sdst + 32768 + off, pWh + off);
        cp16(sdst + 49152 + off, pWl + off);
    }
    CP_COMMIT();
}

__global__ __launch_bounds__(256, 1) void gemm_tc(
    const __nv_bfloat16* __restrict__ Ahi, const __nv_bfloat16* __restrict__ Alo,
    const __nv_bfloat16* __restrict__ Whi, const __nv_bfloat16* __restrict__ Wlo,
    const float* __restrict__ b1, const float* __restrict__ b2, int NKT)
{
    extern __shared__ __align__(16) char dsm[];
    char* bp = dsm + ((1024u - (smem_u32(dsm) & 1023u)) & 1023u);

    const int tid  = threadIdx.x;
    const int lane = tid & 31;
    const int wid  = tid >> 5;
    const int nt = blockIdx.x;
    const int mt = blockIdx.y;

    const int wm = (wid >> 2) * 64;
    const int wn = (wid & 3) * 32;

    const int a_row = lane & 15;
    const int a_cb  = (lane >> 4) * 16;
    const int b_row = (lane & 7) + ((lane >> 4) << 3);
    const int b_cb  = (lane & 8) ? 16 : 0;

    const char* gAh = (const char*)Ahi + (size_t)mt * NKT * TILEB;
    const char* gAl = (const char*)Alo + (size_t)mt * NKT * TILEB;
    const char* gWh = (const char*)Whi + (size_t)nt * NKT * TILEB;
    const char* gWl = (const char*)Wlo + (size_t)nt * NKT * TILEB;

    const uint32_t s0 = smem_u32(bp);

    float acc[4][4][4];
    #pragma unroll
    for (int i = 0; i < 4; i++)
        #pragma unroll
        for (int j = 0; j < 4; j++)
            #pragma unroll
            for (int e = 0; e < 4; e++) acc[i][j][e] = 0.0f;

    stage_cp(s0, gAh, gAl, gWh, gWl, tid);
    if (NKT > 1)
        stage_cp(s0 + STAGEB, gAh + TILEB, gAl + TILEB, gWh + TILEB, gWl + TILEB, tid);

    for (int kt = 0; kt < NKT; kt++) {
        if (kt + 1 < NKT) CP_WAIT(1); else CP_WAIT(0);
        __syncthreads();

        const uint32_t sb = s0 + (kt & 1) * STAGEB;

        #pragma unroll
        for (int kc = 0; kc < 4; kc++) {
            const int kb = kc * 32;
            uint32_t ah[4][4], al[4][4], bh[2][4], bl[2][4];
            #pragma unroll
            for (int mi = 0; mi < 4; mi++) {
                uint32_t off = swz((uint32_t)((wm + mi * 16 + a_row) * 128 + a_cb + kb));
                ldsm4(ah[mi], sb + off);
                ldsm4(al[mi], sb + 16384 + off);
            }
            #pragma unroll
            for (int p = 0; p < 2; p++) {
                uint32_t off = swz((uint32_t)((wn + p * 16 + b_row) * 128 + b_cb + kb));
                ldsm4(bh[p], sb + 32768 + off);
                ldsm4(bl[p], sb + 49152 + off);
            }
            #pragma unroll
            for (int mi = 0; mi < 4; mi++) {
                #pragma unroll
                for (int nj = 0; nj < 4; nj++) {
                    const int p = nj >> 1, h = (nj & 1) * 2;
                    mma_bf16(acc[mi][nj], ah[mi], bh[p][h], bh[p][h + 1]);
                    mma_bf16(acc[mi][nj], ah[mi], bl[p][h], bl[p][h + 1]);
                    mma_bf16(acc[mi][nj], al[mi], bh[p][h], bh[p][h + 1]);
                }
            }
        }

        if (kt + 2 < NKT) {
            __syncthreads();
            const size_t tb = (size_t)(kt + 2) * TILEB;
            stage_cp(s0 + (kt & 1) * STAGEB,
                     gAh + tb, gAl + tb, gWh + tb, gWl + tb, tid);
        }
    }
    __syncthreads();

    float* bias_s = (float*)bp;
    if (tid < 128) bias_s[tid] = b1[nt * 128 + tid] + b2[nt * 128 + tid];
    __syncthreads();

    const int g = lane >> 2, cp2 = (lane & 3) * 2;
    #pragma unroll
    for (int mi = 0; mi < 4; mi++) {
        #pragma unroll
        for (int nj = 0; nj < 4; nj++) {
            const int col = wn + nj * 8 + cp2;
            const float bx = bias_s[col], by = bias_s[col + 1];
            const size_t r0 = (size_t)(mt * 128 + wm + mi * 16 + g) * NOUT + nt * 128 + col;
            const size_t r1 = r0 + 8 * NOUT;
            *(float2*)(g_xp + r0) = make_float2(acc[mi][nj][0] + bx, acc[mi][nj][1] + by);
            *(float2*)(g_xp + r1) = make_float2(acc[mi][nj][2] + bx, acc[mi][nj][3] + by);
        }
    }
}

// ---------------------------------------------------------------------------
// Recurrent scan, CLUSTER-FREE: one CTA per (direction, batch), 512 threads.
// Thread t: output jl = t & 255, k-half c = t >> 8 (128 k-values, 64 packed
// regs — identical matvec body to R14). All 256 h values live in ONE CTA's
// smem: no DSMEM, no mbarriers, no cross-CTA latency in the recurrence.
// R14's combine trick kept: only the c=1 half spills part[]; tid<256 keeps
// its partial in a register and owns the serial tail (tanh + stores).
// Grid = 64, no cluster attribute.
// ---------------------------------------------------------------------------
__global__ __launch_bounds__(512, 1)
void rnn_scan(const float* __restrict__ Whh,
              float* __restrict__ outp,
              int store_mode)
{
    __shared__ __align__(16) float hbuf[2][Hh];
    __shared__ __align__(16) float part[256];

    const int tid = threadIdx.x;
    const int d   = blockIdx.x >> 5;
    const int b   = blockIdx.x & 31;
    const int jl  = tid & 255;          // output unit (0..255)
    const int c   = tid >> 8;           // k-half (0..1)

    // weights: W[d][jl][c*128 .. c*128+128) -> 64 packed ull in registers
    ull wreg[64];
    {
        const ulonglong2* wr =
            (const ulonglong2*)(Whh + ((size_t)d * Hh + jl) * Hh + c * 128);
        #pragma unroll
        for (int q = 0; q < 32; q++) {
            ulonglong2 v = wr[q];
            wreg[2 * q]     = v.x;
            wreg[2 * q + 1] = v.y;
        }
    }

    if (tid < Hh) {
        hbuf[0][tid] = 0.0f;
        hbuf[1][tid] = 0.0f;
    }
    __syncthreads();

    const int xcol  = d * Hh + jl;                      // valid for tid<256
    const int dstep = (d ? -1 : 1) * (Bsz * NOUT);
    const float* xp = g_xp + (size_t)(d ? (Tt - 1) : 0) * (Bsz * NOUT)
                           + (size_t)b * NOUT + xcol;
    float xv = (tid < 256) ? __ldg(xp) : 0.0f;

    const int ktile = xcol >> 6;
    const uint32_t ccol = (uint32_t)((xcol & 63) * 2);

    int cur = 0;

    #pragma unroll 1
    for (int s = 0; s < Tt; s++) {
        // partial matvec: 128 k-values (32 ulonglong2 h-loads, 64 FFMA2)
        ull a0 = 0ull, a1 = 0ull, a2 = 0ull, a3 = 0ull;
        const ulonglong2* hp = (const ulonglong2*)&hbuf[cur][c * 128];
        #pragma unroll
        for (int q = 0; q < 32; q += 2) {
            ulonglong2 h0 = hp[q];
            ulonglong2 h1 = hp[q + 1];
            ffma2(a0, wreg[2 * q],     h0.x);
            ffma2(a1, wreg[2 * q + 1], h0.y);
            ffma2(a2, wreg[2 * q + 2], h1.x);
            ffma2(a3, wreg[2 * q + 3], h1.y);
        }
        float2 p0 = up2(a0), p1 = up2(a1), p2 = up2(a2), p3 = up2(a3);
        float partial = ((p0.x + p0.y) + (p1.x + p1.y))
                      + ((p2.x + p2.y) + (p3.x + p3.y));
        if (tid >= 256) part[tid - 256] = partial;   // only k-half-1 spills
        __syncthreads();

        if (tid < 256) {
            const float z = partial + part[tid] + xv;
            const float h = tanh_acc(z);
            const int t = d ? (Tt - 1 - s) : s;
            const int nb = cur ^ 1;

            // issue next xv load first so it overlaps the store tail
            if (s + 1 < Tt) {
                xp += dstep;
                xv = __ldg(xp);
            }

            hbuf[nb][tid] = h;                         // full vector, local

            if (store_mode == 0) {
                const int m = t * Bsz + b;
                const int mt2 = m >> 7, r = m & 127;
                const size_t tb = (size_t)(mt2 * NKT1 + ktile) * TILEB;
                const uint32_t off = swz((uint32_t)(r * 128) + ccol);
                __nv_bfloat16 hi = __float2bfloat16_rn(h);
                __nv_bfloat16 lo = __float2bfloat16_rn(h - __bfloat162float(hi));
                *(__nv_bfloat16*)((char*)g_H1hi + tb + off) = hi;
                *(__nv_bfloat16*)((char*)g_H1lo + tb + off) = lo;
            } else {
                outp[((size_t)b * Tt + t) * NOUT + xcol] = h;
            }
        }
        __syncthreads();   // h(nb) visible CTA-wide; part[] reusable

        cur ^= 1;
    }
}

// ---------------------------------------------------------------------------
// Launch
// ---------------------------------------------------------------------------
extern "C" void kernel_launch(void* const* d_in, const int* in_sizes, int n_in,
                              void* d_out, int out_size)
{
    (void)in_sizes; (void)n_in; (void)out_size;
    const float* x    = (const float*)d_in[0];
    const float* Wih0 = (const float*)d_in[1];
    const float* Whh0 = (const float*)d_in[2];
    const float* bih0 = (const float*)d_in[3];
    const float* bhh0 = (const float*)d_in[4];
    const float* Wih1 = (const float*)d_in[5];
    const float* Whh1 = (const float*)d_in[6];
    const float* bih1 = (const float*)d_in[7];
    const float* bhh1 = (const float*)d_in[8];
    float* out = (float*)d_out;

    __nv_bfloat16 *Ahi_p, *Alo_p, *W0hi_p, *W0lo_p, *H1hi_p, *H1lo_p, *W1hi_p, *W1lo_p;
    cudaGetSymbolAddress((void**)&Ahi_p,  g_Ahi);
    cudaGetSymbolAddress((void**)&Alo_p,  g_Alo);
    cudaGetSymbolAddress((void**)&W0hi_p, g_W0hi);
    cudaGetSymbolAddress((void**)&W0lo_p, g_W0lo);
    cudaGetSymbolAddress((void**)&H1hi_p, g_H1hi);
    cudaGetSymbolAddress((void**)&H1lo_p, g_H1lo);
    cudaGetSymbolAddress((void**)&W1hi_p, g_W1hi);
    cudaGetSymbolAddress((void**)&W1lo_p, g_W1lo);

    cudaFuncSetAttribute(gemm_tc, cudaFuncAttributeMaxDynamicSharedMemorySize,
                         GEMM_SMEM);

    conv_bf16<<<(Mrows * (Ii / 8) + 255) / 256, 256>>>(x, Ahi_p, Alo_p, Ii, 0,
                                                       Mrows * (Ii / 8));
    conv_bf16<<<(NOUT * (Ii / 8) + 255) / 256, 256>>>(Wih0, W0hi_p, W0lo_p, Ii, 1,
                                                      NOUT * (Ii / 8));
    conv_bf16<<<(NOUT * (NOUT / 8) + 255) / 256, 256>>>(Wih1, W1hi_p, W1lo_p, NOUT, 1,
                                                        NOUT * (NOUT / 8));

    dim3 gg(NOUT / 128, Mrows / 128);   // (4, 256)

    gemm_tc<<<gg, 256, GEMM_SMEM>>>(Ahi_p, Alo_p, W0hi_p, W0lo_p, bih0, bhh0, NKT0);
    rnn_scan<<<64, 512>>>(Whh0, nullptr, 0);

    gemm_tc<<<gg, 256, GEMM_SMEM>>>(H1hi_p, H1lo_p, W1hi_p, W1lo_p, bih1, bhh1, NKT1);
    rnn_scan<<<64, 512>>>(Whh1, out, 1);
}

// round 16
// speedup vs baseline: 2.6121x; 2.6121x over previous
#include <cuda_runtime.h>
#include <cuda_bf16.h>
#include <cstddef>
#include <cstdint>

#define Bsz  32
#define Tt   1024
#define Ii   1024
#define Hh   256
#define NOUT 512   // 2*H
#define Mrows (Bsz * Tt)        // 32768
#define NKT0 16                 // 1024/64 k-tiles (layer0)
#define NKT1 8                  // 512/64 k-tiles (layer1)
#define TILEB 16384             // bytes per 128x64 bf16 tile
#define STAGEB 65536            // 4 tiles (Ahi,Alo,Whi,Wlo)
#define GEMM_SMEM (2 * STAGEB + 1024)

typedef unsigned long long ull;

// ---------------------------------------------------------------------------
// Device scratch (allocation-free rule: __device__ globals)
// ---------------------------------------------------------------------------
__device__ float g_xp[(size_t)Mrows * NOUT];                 // projections
__device__ __align__(256) __nv_bfloat16 g_Ahi[(size_t)Mrows * Ii];
__device__ __align__(256) __nv_bfloat16 g_Alo[(size_t)Mrows * Ii];
__device__ __align__(256) __nv_bfloat16 g_H1hi[(size_t)Mrows * NOUT];
__device__ __align__(256) __nv_bfloat16 g_H1lo[(size_t)Mrows * NOUT];
__device__ __align__(256) __nv_bfloat16 g_W0hi[NOUT * Ii];
__device__ __align__(256) __nv_bfloat16 g_W0lo[NOUT * Ii];
__device__ __align__(256) __nv_bfloat16 g_W1hi[NOUT * NOUT];
__device__ __align__(256) __nv_bfloat16 g_W1lo[NOUT * NOUT];

// ---------------------------------------------------------------------------
// Helpers
// ---------------------------------------------------------------------------
__device__ __forceinline__ uint32_t swz(uint32_t x) { return x ^ ((x >> 3) & 0x70); }

__device__ __forceinline__ void ffma2(ull& acc, ull a, ull b) {
    asm("fma.rn.f32x2 %0, %1, %2, %0;" : "+l"(acc) : "l"(a), "l"(b));
}
__device__ __forceinline__ float2 up2(ull v) {
    float2 r;
    asm("mov.b64 {%0, %1}, %2;" : "=f"(r.x), "=f"(r.y) : "l"(v));
    return r;
}
__device__ __forceinline__ float tanh_acc(float z) {
    float az = fabsf(z);
    float e  = exp2f(az * 2.885390081777927f);
    float r  = 1.0f - __fdividef(2.0f, e + 1.0f);
    return copysignf(r, z);
}
__device__ __forceinline__ uint32_t smem_u32(const void* p) {
    uint32_t a;
    asm("{ .reg .u64 t; cvta.to.shared.u64 t, %1; cvt.u32.u64 %0, t; }"
        : "=r"(a) : "l"(p));
    return a;
}
__device__ __forceinline__ uint32_t ctarank() {
    uint32_t r;
    asm("mov.u32 %0, %%cluster_ctarank;" : "=r"(r));
    return r;
}
__device__ __forceinline__ uint32_t mapa_u32(uint32_t laddr, uint32_t trank) {
    uint32_t r;
    asm("mapa.shared::cluster.u32 %0, %1, %2;" : "=r"(r) : "r"(laddr), "r"(trank));
    return r;
}
// st.async f32: remote smem store delivering a 4-byte complete_tx to the
// remote CTA's mbarrier (R9/R14-proven publish path).
__device__ __forceinline__ void st_async_f32(uint32_t raddr, float v, uint32_t rmbar) {
    asm volatile(
        "st.async.shared::cluster.mbarrier::complete_tx::bytes.f32 [%0], %1, [%2];"
        :: "r"(raddr), "f"(v), "r"(rmbar) : "memory");
}
__device__ __forceinline__ void mbar_expect_tx(uint32_t mbar, uint32_t bytes) {
    asm volatile("mbarrier.arrive.expect_tx.shared.b64 _, [%0], %1;"
                 :: "r"(mbar), "r"(bytes) : "memory");
}
__device__ __forceinline__ void mbar_wait_cta(uint32_t mbar, uint32_t parity) {
    asm volatile(
        "{\n\t.reg .pred P;\n\t"
        "W%=:\n\t"
        "mbarrier.try_wait.parity.acquire.cta.shared::cta.b64 P, [%0], %1, 0x989680;\n\t"
        "@P bra.uni D%=;\n\tbra.uni W%=;\n\tD%=:\n\t}"
        :: "r"(mbar), "r"(parity) : "memory");
}
#define MBARRIER_INIT(addr, cnt) \
    asm volatile("mbarrier.init.shared.b64 [%0], %1;" :: "r"(addr), "r"(cnt) : "memory")

// generic tensor-core path (compute_80+ PTX, compiles at compute_103)
__device__ __forceinline__ void ldsm4(uint32_t* r, uint32_t addr) {
    asm volatile("ldmatrix.sync.aligned.m8n8.x4.shared.b16 {%0,%1,%2,%3}, [%4];"
                 : "=r"(r[0]), "=r"(r[1]), "=r"(r[2]), "=r"(r[3]) : "r"(addr));
}
__device__ __forceinline__ void mma_bf16(float* c, const uint32_t* a,
                                         uint32_t b0, uint32_t b1) {
    asm volatile(
        "mma.sync.aligned.m16n8k16.row.col.f32.bf16.bf16.f32 "
        "{%0,%1,%2,%3}, {%4,%5,%6,%7}, {%8,%9}, {%0,%1,%2,%3};"
        : "+f"(c[0]), "+f"(c[1]), "+f"(c[2]), "+f"(c[3])
        : "r"(a[0]), "r"(a[1]), "r"(a[2]), "r"(a[3]), "r"(b0), "r"(b1));
}
__device__ __forceinline__ void cp16(uint32_t sdst, const void* gsrc) {
    asm volatile("cp.async.cg.shared.global [%0], [%1], 16;"
                 :: "r"(sdst), "l"(gsrc) : "memory");
}
#define CP_COMMIT() asm volatile("cp.async.commit_group;" ::: "memory")
#define CP_WAIT(n)  asm volatile("cp.async.wait_group %0;" :: "n"(n) : "memory")

// ---------------------------------------------------------------------------
// fp32 -> (hi, lo) bf16 split, written into SW128-swizzled 128x64 tiles.
// ---------------------------------------------------------------------------
__global__ __launch_bounds__(256) void conv_bf16(
    const float* __restrict__ src,
    __nv_bfloat16* __restrict__ dhi,
    __nv_bfloat16* __restrict__ dlo,
    int K, int mode, int total)
{
    int idx = blockIdx.x * 256 + threadIdx.x;
    if (idx >= total) return;
    const int gpr = K >> 3;
    const int m = idx / gpr;
    const int k = (idx - m * gpr) << 3;

    const float* s = (mode == 0)
        ? src + (((size_t)(m & 31) * Tt + (m >> 5)) * K + k)
        : src + ((size_t)m * K + k);
    float4 v0 = *(const float4*)s;
    float4 v1 = *(const float4*)(s + 4);
    float f[8] = {v0.x, v0.y, v0.z, v0.w, v1.x, v1.y, v1.z, v1.w};

    uint32_t hw[4], lw[4];
    #pragma unroll
    for (int i = 0; i < 4; i++) {
        __nv_bfloat16 ha = __float2bfloat16_rn(f[2 * i]);
        __nv_bfloat16 hb = __float2bfloat16_rn(f[2 * i + 1]);
        __nv_bfloat16 la = __float2bfloat16_rn(f[2 * i]     - __bfloat162float(ha));
        __nv_bfloat16 lb = __float2bfloat16_rn(f[2 * i + 1] - __bfloat162float(hb));
        hw[i] = (uint32_t)__bfloat16_as_ushort(ha) | ((uint32_t)__bfloat16_as_ushort(hb) << 16);
        lw[i] = (uint32_t)__bfloat16_as_ushort(la) | ((uint32_t)__bfloat16_as_ushort(lb) << 16);
    }

    const int mt = m >> 7, r = m & 127, kt = k >> 6, c = k & 63;
    size_t off = ((size_t)(mt * (K >> 6) + kt)) * TILEB + swz((uint32_t)(r * 128 + c * 2));
    *(uint4*)((char*)dhi + off) = make_uint4(hw[0], hw[1], hw[2], hw[3]);
    *(uint4*)((char*)dlo + off) = make_uint4(lw[0], lw[1], lw[2], lw[3]);
}

// ---------------------------------------------------------------------------
// bf16x3 tensor-core GEMM (mma.sync): g_xp = A.W^T + b1 + b2   (unchanged)
// ---------------------------------------------------------------------------
__device__ __forceinline__ void stage_cp(
    uint32_t sdst, const char* pAh, const char* pAl,
    const char* pWh, const char* pWl, int tid)
{
    #pragma unroll
    for (int i = 0; i < 4; i++) {
        const int off = tid * 16 + i * 4096;
        cp16(sdst + off,         pAh + off);
        cp16(sdst + 16384 + off, pAl + off);
        cp16(sdst + 32768 + off, pWh + off);
        cp16(sdst + 49152 + off, pWl + off);
    }
    CP_COMMIT();
}

__global__ __launch_bounds__(256, 1) void gemm_tc(
    const __nv_bfloat16* __restrict__ Ahi, const __nv_bfloat16* __restrict__ Alo,
    const __nv_bfloat16* __restrict__ Whi, const __nv_bfloat16* __restrict__ Wlo,
    const float* __restrict__ b1, const float* __restrict__ b2, int NKT)
{
    extern __shared__ __align__(16) char dsm[];
    char* bp = dsm + ((1024u - (smem_u32(dsm) & 1023u)) & 1023u);

    const int tid  = threadIdx.x;
    const int lane = tid & 31;
    const int wid  = tid >> 5;
    const int nt = blockIdx.x;
    const int mt = blockIdx.y;

    const int wm = (wid >> 2) * 64;
    const int wn = (wid & 3) * 32;

    const int a_row = lane & 15;
    const int a_cb  = (lane >> 4) * 16;
    const int b_row = (lane & 7) + ((lane >> 4) << 3);
    const int b_cb  = (lane & 8) ? 16 : 0;

    const char* gAh = (const char*)Ahi + (size_t)mt * NKT * TILEB;
    const char* gAl = (const char*)Alo + (size_t)mt * NKT * TILEB;
    const char* gWh = (const char*)Whi + (size_t)nt * NKT * TILEB;
    const char* gWl = (const char*)Wlo + (size_t)nt * NKT * TILEB;

    const uint32_t s0 = smem_u32(bp);

    float acc[4][4][4];
    #pragma unroll
    for (int i = 0; i < 4; i++)
        #pragma unroll
        for (int j = 0; j < 4; j++)
            #pragma unroll
            for (int e = 0; e < 4; e++) acc[i][j][e] = 0.0f;

    stage_cp(s0, gAh, gAl, gWh, gWl, tid);
    if (NKT > 1)
        stage_cp(s0 + STAGEB, gAh + TILEB, gAl + TILEB, gWh + TILEB, gWl + TILEB, tid);

    for (int kt = 0; kt < NKT; kt++) {
        if (kt + 1 < NKT) CP_WAIT(1); else CP_WAIT(0);
        __syncthreads();

        const uint32_t sb = s0 + (kt & 1) * STAGEB;

        #pragma unroll
        for (int kc = 0; kc < 4; kc++) {
            const int kb = kc * 32;
            uint32_t ah[4][4], al[4][4], bh[2][4], bl[2][4];
            #pragma unroll
            for (int mi = 0; mi < 4; mi++) {
                uint32_t off = swz((uint32_t)((wm + mi * 16 + a_row) * 128 + a_cb + kb));
                ldsm4(ah[mi], sb + off);
                ldsm4(al[mi], sb + 16384 + off);
            }
            #pragma unroll
            for (int p = 0; p < 2; p++) {
                uint32_t off = swz((uint32_t)((wn + p * 16 + b_row) * 128 + b_cb + kb));
                ldsm4(bh[p], sb + 32768 + off);
                ldsm4(bl[p], sb + 49152 + off);
            }
            #pragma unroll
            for (int mi = 0; mi < 4; mi++) {
                #pragma unroll
                for (int nj = 0; nj < 4; nj++) {
                    const int p = nj >> 1, h = (nj & 1) * 2;
                    mma_bf16(acc[mi][nj], ah[mi], bh[p][h], bh[p][h + 1]);
                    mma_bf16(acc[mi][nj], ah[mi], bl[p][h], bl[p][h + 1]);
                    mma_bf16(acc[mi][nj], al[mi], bh[p][h], bh[p][h + 1]);
                }
            }
        }

        if (kt + 2 < NKT) {
            __syncthreads();
            const size_t tb = (size_t)(kt + 2) * TILEB;
            stage_cp(s0 + (kt & 1) * STAGEB,
                     gAh + tb, gAl + tb, gWh + tb, gWl + tb, tid);
        }
    }
    __syncthreads();

    float* bias_s = (float*)bp;
    if (tid < 128) bias_s[tid] = b1[nt * 128 + tid] + b2[nt * 128 + tid];
    __syncthreads();

    const int g = lane >> 2, cp2 = (lane & 3) * 2;
    #pragma unroll
    for (int mi = 0; mi < 4; mi++) {
        #pragma unroll
        for (int nj = 0; nj < 4; nj++) {
            const int col = wn + nj * 8 + cp2;
            const float bx = bias_s[col], by = bias_s[col + 1];
            const size_t r0 = (size_t)(mt * 128 + wm + mi * 16 + g) * NOUT + nt * 128 + col;
            const size_t r1 = r0 + 8 * NOUT;
            *(float2*)(g_xp + r0) = make_float2(acc[mi][nj][0] + bx, acc[mi][nj][1] + by);
            *(float2*)(g_xp + r1) = make_float2(acc[mi][nj][2] + bx, acc[mi][nj][3] + by);
        }
    }
}

// ---------------------------------------------------------------------------
// Recurrent scan, cluster-of-2, 256 threads. R14 structure with an
// ARRIVAL-GATED asymmetric k-split:
//   tid<128  (A, owns output jl=tid + serial tail): k-half = OWN rank's half
//            -> reads only locally-written hbuf slots, NEVER waits on mbar.
//            Its matvec overlaps the peer's DSMEM flight.
//   tid>=128 (B): k-half = peer's half -> alone executes the mbar wait,
//            moved to the TOP of the step (mbar[(s-1)&1], parity
//            ((s-1)>>1)&1; s=0 skips, hbuf zero-init). B's matvec then runs
//            at 1 warp/SMSP (128-cyc issue floor) as the only post-wait work.
// Publish protocol, barriers, stores: byte-identical to R14.
// ---------------------------------------------------------------------------
__global__ __launch_bounds__(256, 1) __cluster_dims__(2, 1, 1)
void rnn_scan(const float* __restrict__ Whh,
              float* __restrict__ outp,
              int store_mode)
{
    __shared__ __align__(16) float hbuf[2][Hh];
    __shared__ __align__(16) float part[128];
    __shared__ __align__(8)  ull   mbar[2];

    const int tid  = threadIdx.x;
    const uint32_t rank = ctarank();
    const int pair = blockIdx.x >> 1;
    const int d    = pair >> 5;
    const int b    = pair & 31;
    const int jl   = tid & 127;
    // rank-dependent k-half: A threads take the LOCAL half, B the peer half
    const int ceff = (tid < 128) ? (int)rank : (int)(rank ^ 1u);
    const int j    = (int)rank * 128 + jl;

    // weights: W[d][j][ceff*128 .. ceff*128+128) -> 64 packed ull in regs
    ull wreg[64];
    {
        const ulonglong2* wr =
            (const ulonglong2*)(Whh + ((size_t)d * Hh + j) * Hh + ceff * 128);
        #pragma unroll
        for (int q = 0; q < 32; q++) {
            ulonglong2 v = wr[q];
            wreg[2 * q]     = v.x;
            wreg[2 * q + 1] = v.y;
        }
    }

    hbuf[0][tid] = 0.0f;
    hbuf[1][tid] = 0.0f;

    const uint32_t mb0 = smem_u32(&mbar[0]);
    const uint32_t mb1 = smem_u32(&mbar[1]);
    if (tid == 0) { MBARRIER_INIT(mb0, 1); MBARRIER_INIT(mb1, 1); }
    __syncthreads();
    asm volatile("barrier.cluster.arrive.aligned;" ::: "memory");
    asm volatile("barrier.cluster.wait.aligned;" ::: "memory");

    const uint32_t peer = rank ^ 1u;
    const uint32_t remMb0 = mapa_u32(mb0, peer);
    const uint32_t remMb1 = mapa_u32(mb1, peer);
    uint32_t remH0 = 0, remH1 = 0;
    if (tid < 128) {
        remH0 = mapa_u32(smem_u32(&hbuf[0][rank * 128 + tid]), peer);
        remH1 = mapa_u32(smem_u32(&hbuf[1][rank * 128 + tid]), peer);
    }

    const int xcol  = d * Hh + (int)rank * 128 + tid;   // valid for tid<128
    const int dstep = (d ? -1 : 1) * (Bsz * NOUT);
    const float* xp = g_xp + (size_t)(d ? (Tt - 1) : 0) * (Bsz * NOUT)
                           + (size_t)b * NOUT + xcol;
    float xv = (tid < 128) ? __ldg(xp) : 0.0f;

    const int ktile = xcol >> 6;
    const uint32_t ccol = (uint32_t)((xcol & 63) * 2);

    int cur = 0;

    #pragma unroll 1
    for (int s = 0; s < Tt; s++) {
        // post this step's expected 512 bytes (128 x 4B st.async from peer)
        if (tid == 0) mbar_expect_tx((s & 1) ? mb1 : mb0, 512u);

        // B threads gate on the peer data for THIS step's read buffer
        // (published during step s-1 -> mbar[(s-1)&1]); A threads never wait.
        if (tid >= 128 && s > 0) {
            const int sm1 = s - 1;
            mbar_wait_cta((sm1 & 1) ? mb1 : mb0, (sm1 >> 1) & 1);
        }

        // partial matvec: 128 k-values (32 ulonglong2 h-loads, 64 FFMA2)
        ull a0 = 0ull, a1 = 0ull, a2 = 0ull, a3 = 0ull;
        const ulonglong2* hp = (const ulonglong2*)&hbuf[cur][ceff * 128];
        #pragma unroll
        for (int q = 0; q < 32; q += 2) {
            ulonglong2 h0 = hp[q];
            ulonglong2 h1 = hp[q + 1];
            ffma2(a0, wreg[2 * q],     h0.x);
            ffma2(a1, wreg[2 * q + 1], h0.y);
            ffma2(a2, wreg[2 * q + 2], h1.x);
            ffma2(a3, wreg[2 * q + 3], h1.y);
        }
        float2 p0 = up2(a0), p1 = up2(a1), p2 = up2(a2), p3 = up2(a3);
        float partial = ((p0.x + p0.y) + (p1.x + p1.y))
                      + ((p2.x + p2.y) + (p3.x + p3.y));
        if (tid >= 128) part[tid - 128] = partial;   // only peer-half spills
        __syncthreads();

        if (tid < 128) {
            const float z = partial + part[tid] + xv;
            const float h = tanh_acc(z);
            const int t = d ? (Tt - 1 - s) : s;
            const int nb = cur ^ 1;

            // issue next xv load first so it overlaps the publish tail
            if (s + 1 < Tt) {
                xp += dstep;
                xv = __ldg(xp);
            }

            hbuf[nb][rank * 128 + tid] = h;                    // local half
            st_async_f32(nb ? remH1 : remH0, h,                // peer half +
                         (s & 1) ? remMb1 : remMb0);           // 4B complete_tx

            if (store_mode == 0) {
                const int m = t * Bsz + b;
                const int mt2 = m >> 7, r = m & 127;
                const size_t tb = (size_t)(mt2 * NKT1 + ktile) * TILEB;
                const uint32_t off = swz((uint32_t)(r * 128) + ccol);
                __nv_bfloat16 hi = __float2bfloat16_rn(h);
                __nv_bfloat16 lo = __float2bfloat16_rn(h - __bfloat162float(hi));
                *(__nv_bfloat16*)((char*)g_H1hi + tb + off) = hi;
                *(__nv_bfloat16*)((char*)g_H1lo + tb + off) = lo;
            } else {
                outp[((size_t)b * Tt + t) * NOUT + xcol] = h;
            }
        }
        __syncthreads();   // local half visible CTA-wide; part[] reusable

        cur ^= 1;
    }

    asm volatile("barrier.cluster.arrive.aligned;" ::: "memory");
    asm volatile("barrier.cluster.wait.aligned;" ::: "memory");
}

// ---------------------------------------------------------------------------
// Launch
// ---------------------------------------------------------------------------
extern "C" void kernel_launch(void* const* d_in, const int* in_sizes, int n_in,
                              void* d_out, int out_size)
{
    (void)in_sizes; (void)n_in; (void)out_size;
    const float* x    = (const float*)d_in[0];
    const float* Wih0 = (const float*)d_in[1];
    const float* Whh0 = (const float*)d_in[2];
    const float* bih0 = (const float*)d_in[3];
    const float* bhh0 = (const float*)d_in[4];
    const float* Wih1 = (const float*)d_in[5];
    const float* Whh1 = (const float*)d_in[6];
    const float* bih1 = (const float*)d_in[7];
    const float* bhh1 = (const float*)d_in[8];
    float* out = (float*)d_out;

    __nv_bfloat16 *Ahi_p, *Alo_p, *W0hi_p, *W0lo_p, *H1hi_p, *H1lo_p, *W1hi_p, *W1lo_p;
    cudaGetSymbolAddress((void**)&Ahi_p,  g_Ahi);
    cudaGetSymbolAddress((void**)&Alo_p,  g_Alo);
    cudaGetSymbolAddress((void**)&W0hi_p, g_W0hi);
    cudaGetSymbolAddress((void**)&W0lo_p, g_W0lo);
    cudaGetSymbolAddress((void**)&H1hi_p, g_H1hi);
    cudaGetSymbolAddress((void**)&H1lo_p, g_H1lo);
    cudaGetSymbolAddress((void**)&W1hi_p, g_W1hi);
    cudaGetSymbolAddress((void**)&W1lo_p, g_W1lo);

    cudaFuncSetAttribute(gemm_tc, cudaFuncAttributeMaxDynamicSharedMemorySize,
                         GEMM_SMEM);

    conv_bf16<<<(Mrows * (Ii / 8) + 255) / 256, 256>>>(x, Ahi_p, Alo_p, Ii, 0,
                                                       Mrows * (Ii / 8));
    conv_bf16<<<(NOUT * (Ii / 8) + 255) / 256, 256>>>(Wih0, W0hi_p, W0lo_p, Ii, 1,
                                                      NOUT * (Ii / 8));
    conv_bf16<<<(NOUT * (NOUT / 8) + 255) / 256, 256>>>(Wih1, W1hi_p, W1lo_p, NOUT, 1,
                                                        NOUT * (NOUT / 8));

    dim3 gg(NOUT / 128, Mrows / 128);   // (4, 256)

    gemm_tc<<<gg, 256, GEMM_SMEM>>>(Ahi_p, Alo_p, W0hi_p, W0lo_p, bih0, bhh0, NKT0);
    rnn_scan<<<128, 256>>>(Whh0, nullptr, 0);

    gemm_tc<<<gg, 256, GEMM_SMEM>>>(H1hi_p, H1lo_p, W1hi_p, W1lo_p, bih1, bhh1, NKT1);
    rnn_scan<<<128, 256>>>(Whh1, out, 1);
}